// round 4
// baseline (speedup 1.0000x reference)
#include <cuda_runtime.h>
#include <math.h>
#include <stdint.h>

// ---------------- problem constants ----------------
#define BB   2
#define LL   1024
#define DD   768
#define VV   32000
#define NLAYER 4
#define DIN  1536          // d_inner
#define NS   16            // d_state
#define DCV  4             // d_conv
#define DTR  48            // dt_rank
#define XDIM (DTR + 2*NS)  // 80
#define MROWS (BB*LL)      // 2048
#define XSPLIT 8           // split-K factor for x_proj

// ---------------- device scratch (no allocation allowed) ----------------
__device__ float g_x    [MROWS*DD];
__device__ float g_xn   [MROWS*DD];
__device__ float g_xz   [MROWS*2*DIN];
__device__ float g_xbc  [MROWS*DIN];
__device__ float g_xdbl [MROWS*XDIM];
__device__ float g_xpart[XSPLIT*MROWS*XDIM];
__device__ float g_dlt  [MROWS*DIN];
__device__ float g_y    [MROWS*DIN];

// ---------------- helpers ----------------
__device__ __forceinline__ float softplusf(float x) {
    return fmaxf(x, 0.f) + log1pf(expf(-fabsf(x)));
}
__device__ __forceinline__ float siluf(float x) {
    return x / (1.f + expf(-x));
}
__device__ __forceinline__ uint32_t to_tf32(float f) {
    uint32_t u;
    asm("cvt.rna.tf32.f32 %0, %1;" : "=r"(u) : "f"(f));
    return u;
}

// ---------------- warmup/dummy: shifts ncu capture window ----------------
__global__ void warm_kernel() {
    if (threadIdx.x == 0) g_xpart[0] = 0.f;
}

// ---------------- embedding gather ----------------
__global__ void embed_kernel(const int* __restrict__ tok,
                             const float* __restrict__ emb) {
    int idx = blockIdx.x * blockDim.x + threadIdx.x;
    if (idx >= MROWS * DD) return;
    int row = idx / DD, d = idx - row * DD;
    g_x[idx] = emb[tok[row] * DD + d];
}

// ---------------- rmsnorm: one block per row ----------------
__global__ void rmsnorm_kernel(const float* __restrict__ w) {
    int row = blockIdx.x;
    const float* xr = g_x + row * DD;
    float s = 0.f;
    for (int i = threadIdx.x; i < DD; i += 256) { float v = xr[i]; s += v * v; }
    __shared__ float red[8];
    #pragma unroll
    for (int o = 16; o; o >>= 1) s += __shfl_xor_sync(~0u, s, o);
    if ((threadIdx.x & 31) == 0) red[threadIdx.x >> 5] = s;
    __syncthreads();
    if (threadIdx.x < 8) {
        float v = red[threadIdx.x];
        #pragma unroll
        for (int o = 4; o; o >>= 1) v += __shfl_xor_sync(0xff, v, o);
        if (threadIdx.x == 0) red[0] = v;
    }
    __syncthreads();
    float rstd = rsqrtf(red[0] / (float)DD + 1e-5f);
    for (int i = threadIdx.x; i < DD; i += 256)
        g_xn[row * DD + i] = xr[i] * rstd * w[i];
}

// ---------------- causal depthwise conv (DC=4) + silu ----------------
__global__ void conv_silu_kernel(const float* __restrict__ w,
                                 const float* __restrict__ bias) {
    int idx = blockIdx.x * blockDim.x + threadIdx.x;
    if (idx >= MROWS * DIN) return;
    int c = idx % DIN;
    int row = idx / DIN;
    int t = row % LL;
    float acc = bias[c];
    #pragma unroll
    for (int j = 0; j < DCV; j++) {
        int tt = t - (DCV - 1) + j;
        if (tt >= 0)
            acc += w[c * DCV + j] * g_xz[(row - (DCV - 1) + j) * (2 * DIN) + c];
    }
    g_xbc[idx] = siluf(acc);
}

// ---------------- TF32 tensor-core GEMM, fragment-order smem --------------
// C[M,N] = A[M,K] @ W[N,K]^T (+bias)(+softplus)(+resid)
// Tile 128x128, BK=16, 8 warps (warp tile 64x32, 4x4 m16n8k8).
// Shared memory holds tiles permuted into mma fragment order:
//   A element (r in 16, kk in 8) of block (b_m,b_k):
//     lane q=kk&3, fr=r&7, reg j = ((kk>=4)<<1)|(r>=8)
//     slot = q*8+fr; index = slot*4 + j   -> consume = 1 LDS.128/lane/block
//   B element (n in 8, kk in 8): slot = (kk&3)*8 + (n&7); j = kk>=4
//     index = slot*2 + j                  -> consume = 1 LDS.64/lane/block
// If kchunk>0: split-K; CTA z handles k in [z*kchunk,(z+1)*kchunk), writes
// partials at C + z*M*ldc (no bias/act/resid).
__global__ void __launch_bounds__(256, 2)
tgemm_kernel(const float* __restrict__ A, const float* __restrict__ W,
             const float* __restrict__ bias, const float* __restrict__ resid,
             float* __restrict__ C,
             int M, int N, int K, int lda, int ldc, int act, int kchunk) {
    __shared__ __align__(16) uint32_t Asf[2][2][8][128];   // [buf][b_k][b_m][.]
    __shared__ __align__(16) uint32_t Bsf[2][2][16][64];   // [buf][b_k][b_n][.]

    int tid = threadIdx.x;
    int m0 = blockIdx.x * 128, n0 = blockIdx.y * 128;
    int lane = tid & 31, warp = tid >> 5;
    int wm16 = (warp & 1) * 4;          // A block row base (b_m units)
    int wn8  = (warp >> 1) * 4;         // B block col base (b_n units)

    int kbase = 0, kcount = K;
    if (kchunk > 0) {
        kbase = blockIdx.z * kchunk;
        kcount = kchunk;
        C += (size_t)blockIdx.z * M * ldc;
    }

    int sr = tid >> 2;                  // 0..63 staging row
    int sc = (tid & 3) * 4;             // staging k (0,4,8,12)

    const float* Aptr0 = A + (size_t)(m0 + sr) * lda + kbase + sc;
    const float* Aptr1 = A + (size_t)(m0 + sr + 64) * lda + kbase + sc;
    bool wv0 = (n0 + sr) < N;
    bool wv1 = (n0 + sr + 64) < N;
    const float* Wptr0 = W + (size_t)(n0 + sr) * K + kbase + sc;
    const float* Wptr1 = W + (size_t)(n0 + sr + 64) * K + kbase + sc;

    // staging destination constants
    int s_bk = sc >> 3;                  // 0 or 1
    int a_jkk = (sc & 4) >> 1;           // j k-part for A (0 or 2)
    int b_j   = (sc & 4) >> 2;           // j for B (0 or 1)
    int a_bm0 = sr >> 4, a_fr0 = sr & 7, a_rh0 = (sr >> 3) & 1;
    int m1 = sr + 64;
    int a_bm1 = m1 >> 4, a_fr1 = m1 & 7, a_rh1 = (m1 >> 3) & 1;
    int b_bn0 = sr >> 3, b_fn0 = sr & 7;
    int b_bn1 = (sr + 64) >> 3, b_fn1 = sr & 7;

    float acc[4][4][4];
    #pragma unroll
    for (int i = 0; i < 4; i++)
        #pragma unroll
        for (int j = 0; j < 4; j++)
            #pragma unroll
            for (int r = 0; r < 4; r++) acc[i][j][r] = 0.f;

    float4 a0 = *(const float4*)(Aptr0);
    float4 a1 = *(const float4*)(Aptr1);
    float4 w0 = wv0 ? *(const float4*)(Wptr0) : make_float4(0,0,0,0);
    float4 w1 = wv1 ? *(const float4*)(Wptr1) : make_float4(0,0,0,0);

    #define STAGE(bufi)                                                       \
    {                                                                         \
        const float* ap0 = &a0.x; const float* ap1 = &a1.x;                   \
        const float* wp0 = &w0.x; const float* wp1 = &w1.x;                   \
        _Pragma("unroll")                                                     \
        for (int i = 0; i < 4; i++) {                                         \
            Asf[bufi][s_bk][a_bm0][(i*8 + a_fr0)*4 + a_jkk + a_rh0] = to_tf32(ap0[i]); \
            Asf[bufi][s_bk][a_bm1][(i*8 + a_fr1)*4 + a_jkk + a_rh1] = to_tf32(ap1[i]); \
            Bsf[bufi][s_bk][b_bn0][(i*8 + b_fn0)*2 + b_j] = to_tf32(wp0[i]);  \
            Bsf[bufi][s_bk][b_bn1][(i*8 + b_fn1)*2 + b_j] = to_tf32(wp1[i]);  \
        }                                                                     \
    }

    STAGE(0);
    __syncthreads();

    int ntiles = kcount / 16;
    for (int it = 0; it < ntiles; it++) {
        int buf = it & 1;
        bool more = (it + 1) < ntiles;
        if (more) {
            int ks = (it + 1) * 16;
            a0 = *(const float4*)(Aptr0 + ks);
            a1 = *(const float4*)(Aptr1 + ks);
            w0 = wv0 ? *(const float4*)(Wptr0 + ks) : make_float4(0,0,0,0);
            w1 = wv1 ? *(const float4*)(Wptr1 + ks) : make_float4(0,0,0,0);
        }

        int slot = (lane & 3) * 8 + (lane >> 2);     // 0..31
        #pragma unroll
        for (int bk = 0; bk < 2; bk++) {
            uint4 af[4]; uint2 bf[4];
            #pragma unroll
            for (int mt = 0; mt < 4; mt++)
                af[mt] = ((const uint4*)Asf[buf][bk][wm16 + mt])[slot];
            #pragma unroll
            for (int nt = 0; nt < 4; nt++)
                bf[nt] = ((const uint2*)Bsf[buf][bk][wn8 + nt])[slot];
            #pragma unroll
            for (int mt = 0; mt < 4; mt++)
                #pragma unroll
                for (int nt = 0; nt < 4; nt++) {
                    asm volatile(
                        "mma.sync.aligned.m16n8k8.row.col.f32.tf32.tf32.f32 "
                        "{%0,%1,%2,%3}, {%4,%5,%6,%7}, {%8,%9}, {%0,%1,%2,%3};"
                        : "+f"(acc[mt][nt][0]), "+f"(acc[mt][nt][1]),
                          "+f"(acc[mt][nt][2]), "+f"(acc[mt][nt][3])
                        : "r"(af[mt].x), "r"(af[mt].y),
                          "r"(af[mt].z), "r"(af[mt].w),
                          "r"(bf[nt].x), "r"(bf[nt].y));
                }
        }

        if (more) {
            int nb = (it + 1) & 1;
            STAGE(nb);
        }
        __syncthreads();
    }
    #undef STAGE

    // epilogue
    int fr = lane >> 2;
    int fc = (lane & 3) * 2;
    #pragma unroll
    for (int mt = 0; mt < 4; mt++) {
        int row0 = m0 + (warp & 1) * 64 + mt * 16 + fr;
        #pragma unroll
        for (int nt = 0; nt < 4; nt++) {
            int col0 = n0 + (warp >> 1) * 32 + nt * 8 + fc;
            #pragma unroll
            for (int r = 0; r < 4; r++) {
                int m = row0 + (r >> 1) * 8;
                int n = col0 + (r & 1);
                if (n < N) {
                    float v = acc[mt][nt][r];
                    if (bias) v += bias[n];
                    if (act == 1) v = softplusf(v);
                    if (resid) v += resid[(size_t)m * ldc + n];
                    C[(size_t)m * ldc + n] = v;
                }
            }
        }
    }
}

// ---------------- split-K reduction for x_proj ----------------
__global__ void xreduce_kernel() {
    int idx = blockIdx.x * blockDim.x + threadIdx.x;
    if (idx >= MROWS * XDIM) return;
    float s = 0.f;
    #pragma unroll
    for (int z = 0; z < XSPLIT; z++)
        s += g_xpart[(size_t)z * MROWS * XDIM + idx];
    g_xdbl[idx] = s;
}

// ---------------- selective scan: half-warp (16 lanes = 16 states) per (b,d)
__global__ void scan_kernel(const float* __restrict__ A_log,
                            const float* __restrict__ Dvec) {
    int half = threadIdx.x / 16;
    int ch = blockIdx.x * 16 + half;
    int lane = threadIdx.x & 15;
    int b = ch / DIN, d = ch % DIN;

    float An = -__expf(A_log[d * NS + lane]);
    float Dd = Dvec[d];

    const float* dptr = g_dlt  + (size_t)b * LL * DIN + d;
    const float* uptr = g_xbc  + (size_t)b * LL * DIN + d;
    const float* bptr = g_xdbl + (size_t)b * LL * XDIM + DTR + lane;
    const float* cptr = g_xdbl + (size_t)b * LL * XDIM + DTR + NS + lane;
    const float* zptr = g_xz   + (size_t)b * LL * (2 * DIN) + DIN + d;
    float* yptr = g_y + (size_t)b * LL * DIN + d;

    float h = 0.f;
    for (int t = 0; t < LL; t++) {
        float delta = dptr[(size_t)t * DIN];
        float u     = uptr[(size_t)t * DIN];
        float Bn    = bptr[(size_t)t * XDIM];
        float Cn    = cptr[(size_t)t * XDIM];
        float dA = __expf(delta * An);
        h = dA * h + delta * Bn * u;
        float p = h * Cn;
        p += __shfl_xor_sync(~0u, p, 8);
        p += __shfl_xor_sync(~0u, p, 4);
        p += __shfl_xor_sync(~0u, p, 2);
        p += __shfl_xor_sync(~0u, p, 1);
        if (lane == 0) {
            float z = zptr[(size_t)t * (2 * DIN)];
            float yv = p + u * Dd;
            yv *= z / (1.f + __expf(-z));
            yptr[(size_t)t * DIN] = yv;
        }
    }
}

// ---------------- launch ----------------
extern "C" void kernel_launch(void* const* d_in, const int* in_sizes, int n_in,
                              void* d_out, int out_size) {
    const int*   tokens    = (const int*)  d_in[0];
    const float* emb       = (const float*)d_in[1];
    const float* Wout_w    = (const float*)d_in[2];
    const float* Wout_b    = (const float*)d_in[3];
    const float* norm_w    = (const float*)d_in[4];
    const float* in_proj_w = (const float*)d_in[5];
    const float* conv_w    = (const float*)d_in[6];
    const float* conv_b    = (const float*)d_in[7];
    const float* x_proj_w  = (const float*)d_in[8];
    const float* dt_proj_w = (const float*)d_in[9];
    const float* dt_proj_b = (const float*)d_in[10];
    const float* A_log     = (const float*)d_in[11];
    const float* Dvec      = (const float*)d_in[12];
    const float* out_projw = (const float*)d_in[13];
    float* out = (float*)d_out;

    float *x, *xn, *xz, *xbc, *xdbl, *xpart, *dlt, *y;
    cudaGetSymbolAddress((void**)&x,     g_x);
    cudaGetSymbolAddress((void**)&xn,    g_xn);
    cudaGetSymbolAddress((void**)&xz,    g_xz);
    cudaGetSymbolAddress((void**)&xbc,   g_xbc);
    cudaGetSymbolAddress((void**)&xdbl,  g_xdbl);
    cudaGetSymbolAddress((void**)&xpart, g_xpart);
    cudaGetSymbolAddress((void**)&dlt,   g_dlt);
    cudaGetSymbolAddress((void**)&y,     g_y);

    warm_kernel<<<1, 32>>>();
    embed_kernel<<<(MROWS * DD + 255) / 256, 256>>>(tokens, emb);

    for (int l = 0; l < NLAYER; l++) {
        rmsnorm_kernel<<<MROWS, 256>>>(norm_w + (size_t)l * DD);

        // in_proj: (2048 x 3072), K=768
        {
            dim3 g(MROWS / 128, 2 * DIN / 128);
            tgemm_kernel<<<g, 256>>>(xn, in_proj_w + (size_t)l * 2 * DIN * DD,
                                     nullptr, nullptr, xz,
                                     MROWS, 2 * DIN, DD, DD, 2 * DIN, 0, 0);
        }

        conv_silu_kernel<<<(MROWS * DIN + 255) / 256, 256>>>(
            conv_w + (size_t)l * DIN * DCV, conv_b + (size_t)l * DIN);

        // x_proj: (2048 x 80), K=1536, split-K=8 -> partials + reduce
        {
            dim3 g(MROWS / 128, 1, XSPLIT);
            tgemm_kernel<<<g, 256>>>(xbc, x_proj_w + (size_t)l * XDIM * DIN,
                                     nullptr, nullptr, xpart,
                                     MROWS, XDIM, DIN, DIN, XDIM, 0,
                                     DIN / XSPLIT);
            xreduce_kernel<<<(MROWS * XDIM + 255) / 256, 256>>>();
        }

        // dt_proj + bias + softplus: (2048 x 1536), K=48
        {
            dim3 g(MROWS / 128, DIN / 128);
            tgemm_kernel<<<g, 256>>>(xdbl, dt_proj_w + (size_t)l * DIN * DTR,
                                     dt_proj_b + (size_t)l * DIN, nullptr, dlt,
                                     MROWS, DIN, DTR, XDIM, DIN, 1, 0);
        }

        scan_kernel<<<(BB * DIN) / 16, 256>>>(A_log + (size_t)l * DIN * NS,
                                              Dvec + (size_t)l * DIN);

        // out_proj + residual: (2048 x 768), K=1536
        {
            dim3 g(MROWS / 128, DD / 128);
            tgemm_kernel<<<g, 256>>>(y, out_projw + (size_t)l * DD * DIN,
                                     nullptr, x, x,
                                     MROWS, DD, DIN, DIN, DD, 0, 0);
        }
    }

    // logits: (2048 x 32000), K=768, + bias
    {
        dim3 g(MROWS / 128, VV / 128);
        tgemm_kernel<<<g, 256>>>(x, Wout_w, Wout_b, nullptr, out,
                                 MROWS, VV, DD, DD, VV, 0, 0);
    }
}

// round 6
// speedup vs baseline: 1.0322x; 1.0322x over previous
#include <cuda_runtime.h>
#include <math.h>
#include <stdint.h>

// ---------------- problem constants ----------------
#define BB   2
#define LL   1024
#define DD   768
#define VV   32000
#define NLAYER 4
#define DIN  1536          // d_inner
#define NS   16            // d_state
#define DCV  4             // d_conv
#define DTR  48            // dt_rank
#define XDIM (DTR + 2*NS)  // 80
#define MROWS (BB*LL)      // 2048
#define XSPLIT 8           // split-K factor for x_proj

// ---------------- device scratch (no allocation allowed) ----------------
__device__ float g_x    [MROWS*DD];
__device__ float g_xn   [MROWS*DD];
__device__ float g_xz   [MROWS*2*DIN];
__device__ float g_xbc  [MROWS*DIN];
__device__ float g_xdbl [MROWS*XDIM];
__device__ float g_xpart[XSPLIT*MROWS*XDIM];
__device__ float g_dlt  [MROWS*DIN];
__device__ float g_y    [MROWS*DIN];

// ---------------- helpers ----------------
__device__ __forceinline__ float softplusf(float x) {
    return fmaxf(x, 0.f) + log1pf(expf(-fabsf(x)));
}
__device__ __forceinline__ float siluf(float x) {
    return x / (1.f + expf(-x));
}
__device__ __forceinline__ uint32_t to_tf32(float f) {
    uint32_t u;
    asm("cvt.rna.tf32.f32 %0, %1;" : "=r"(u) : "f"(f));
    return u;
}

// ---------------- warmup/dummy: shifts ncu capture window ----------------
__global__ void warm_kernel() {
    if (threadIdx.x == 0) g_xpart[0] = 0.f;
}

// ---------------- embedding gather ----------------
__global__ void embed_kernel(const int* __restrict__ tok,
                             const float* __restrict__ emb) {
    int idx = blockIdx.x * blockDim.x + threadIdx.x;
    if (idx >= MROWS * DD) return;
    int row = idx / DD, d = idx - row * DD;
    g_x[idx] = emb[tok[row] * DD + d];
}

// ---------------- rmsnorm: one block per row ----------------
__global__ void rmsnorm_kernel(const float* __restrict__ w) {
    int row = blockIdx.x;
    const float* xr = g_x + row * DD;
    float s = 0.f;
    for (int i = threadIdx.x; i < DD; i += 256) { float v = xr[i]; s += v * v; }
    __shared__ float red[8];
    #pragma unroll
    for (int o = 16; o; o >>= 1) s += __shfl_xor_sync(~0u, s, o);
    if ((threadIdx.x & 31) == 0) red[threadIdx.x >> 5] = s;
    __syncthreads();
    if (threadIdx.x < 8) {
        float v = red[threadIdx.x];
        #pragma unroll
        for (int o = 4; o; o >>= 1) v += __shfl_xor_sync(0xff, v, o);
        if (threadIdx.x == 0) red[0] = v;
    }
    __syncthreads();
    float rstd = rsqrtf(red[0] / (float)DD + 1e-5f);
    for (int i = threadIdx.x; i < DD; i += 256)
        g_xn[row * DD + i] = xr[i] * rstd * w[i];
}

// ---------------- causal depthwise conv (DC=4) + silu ----------------
__global__ void conv_silu_kernel(const float* __restrict__ w,
                                 const float* __restrict__ bias) {
    int idx = blockIdx.x * blockDim.x + threadIdx.x;
    if (idx >= MROWS * DIN) return;
    int c = idx % DIN;
    int row = idx / DIN;
    int t = row % LL;
    float acc = bias[c];
    #pragma unroll
    for (int j = 0; j < DCV; j++) {
        int tt = t - (DCV - 1) + j;
        if (tt >= 0)
            acc += w[c * DCV + j] * g_xz[(row - (DCV - 1) + j) * (2 * DIN) + c];
    }
    g_xbc[idx] = siluf(acc);
}

// ---------------- TF32 tensor-core GEMM (templated N-width) ---------------
// C[M,N] = A[M,K] @ W[N,K]^T (+bias)(+softplus)(+resid)
// CTA tile 128 x (32*WN), BK=16, 8 warps in 2(m) x 4(n), warp tile 64x(8*WN).
// WN=4: 128x128 (proven R2 config). WN=8: 128x256, 1.0 LDS per mma.
// kchunk>0: split-K; CTA z covers k in [z*kchunk,(z+1)*kchunk), partials at
// C + z*M*ldc (no bias/act/resid).
// Requires M%128==0, K%16==0, A rows 16B-aligned. N guarded.
template<int WN>
__global__ void __launch_bounds__(256)
tgemm_kernel(const float* __restrict__ A, const float* __restrict__ W,
             const float* __restrict__ bias, const float* __restrict__ resid,
             float* __restrict__ C,
             int M, int N, int K, int lda, int ldc, int act, int kchunk) {
    constexpr int BN = 32 * WN;        // 128 or 256
    constexpr int NB = BN / 64;        // 2 or 4 row-groups of B staging
    __shared__ __align__(16) uint32_t As[128][20];
    __shared__ __align__(16) uint32_t Bs[BN][20];

    int tid = threadIdx.x;
    int m0 = blockIdx.x * 128, n0 = blockIdx.y * BN;
    int lane = tid & 31, warp = tid >> 5;
    int wm = (warp & 1) * 64;
    int wn = (warp >> 1) * (8 * WN);

    int kbase = 0, kcount = K;
    if (kchunk > 0) {
        kbase = blockIdx.z * kchunk;
        kcount = kchunk;
        C += (size_t)blockIdx.z * M * ldc;
    }

    int sr = tid >> 2;                 // 0..63 staging row
    int sc = (tid & 3) * 4;            // staging k-col (0,4,8,12)

    const float* Aptr0 = A + (size_t)(m0 + sr) * lda + kbase + sc;
    const float* Aptr1 = A + (size_t)(m0 + sr + 64) * lda + kbase + sc;
    const float* Wptr[NB];
    bool wv[NB];
    #pragma unroll
    for (int i = 0; i < NB; i++) {
        wv[i] = (n0 + sr + 64 * i) < N;
        Wptr[i] = W + (size_t)(n0 + sr + 64 * i) * K + kbase + sc;
    }

    float acc[4][WN][4];
    #pragma unroll
    for (int i = 0; i < 4; i++)
        #pragma unroll
        for (int j = 0; j < WN; j++)
            #pragma unroll
            for (int r = 0; r < 4; r++) acc[i][j][r] = 0.f;

    for (int ks = 0; ks < kcount; ks += 16) {
        // stage A (2 rows/thread) and B (NB rows/thread), tf32-converted
        {
            float4 a0 = *(const float4*)(Aptr0 + ks);
            float4 a1 = *(const float4*)(Aptr1 + ks);
            uint4 ua0, ua1;
            ua0.x = to_tf32(a0.x); ua0.y = to_tf32(a0.y);
            ua0.z = to_tf32(a0.z); ua0.w = to_tf32(a0.w);
            ua1.x = to_tf32(a1.x); ua1.y = to_tf32(a1.y);
            ua1.z = to_tf32(a1.z); ua1.w = to_tf32(a1.w);
            *(uint4*)&As[sr][sc]      = ua0;
            *(uint4*)&As[sr + 64][sc] = ua1;
            #pragma unroll
            for (int i = 0; i < NB; i++) {
                float4 wv4 = wv[i] ? *(const float4*)(Wptr[i] + ks)
                                   : make_float4(0.f, 0.f, 0.f, 0.f);
                uint4 uw;
                uw.x = to_tf32(wv4.x); uw.y = to_tf32(wv4.y);
                uw.z = to_tf32(wv4.z); uw.w = to_tf32(wv4.w);
                *(uint4*)&Bs[sr + 64 * i][sc] = uw;
            }
        }
        __syncthreads();

        #pragma unroll
        for (int kk = 0; kk < 16; kk += 8) {
            uint32_t af[4][4], bf[WN][2];
            int k0 = kk + (lane & 3);
            int fr = lane >> 2;
            #pragma unroll
            for (int mt = 0; mt < 4; mt++) {
                int row = wm + mt * 16 + fr;
                af[mt][0] = As[row][k0];
                af[mt][1] = As[row + 8][k0];
                af[mt][2] = As[row][k0 + 4];
                af[mt][3] = As[row + 8][k0 + 4];
            }
            #pragma unroll
            for (int nt = 0; nt < WN; nt++) {
                int col = wn + nt * 8 + fr;
                bf[nt][0] = Bs[col][k0];
                bf[nt][1] = Bs[col][k0 + 4];
            }
            #pragma unroll
            for (int mt = 0; mt < 4; mt++)
                #pragma unroll
                for (int nt = 0; nt < WN; nt++) {
                    asm volatile(
                        "mma.sync.aligned.m16n8k8.row.col.f32.tf32.tf32.f32 "
                        "{%0,%1,%2,%3}, {%4,%5,%6,%7}, {%8,%9}, {%0,%1,%2,%3};"
                        : "+f"(acc[mt][nt][0]), "+f"(acc[mt][nt][1]),
                          "+f"(acc[mt][nt][2]), "+f"(acc[mt][nt][3])
                        : "r"(af[mt][0]), "r"(af[mt][1]),
                          "r"(af[mt][2]), "r"(af[mt][3]),
                          "r"(bf[nt][0]), "r"(bf[nt][1]));
                }
        }
        __syncthreads();
    }

    // epilogue: float2 stores (n even, N%16==0 so n<N implies n+1<N)
    int fr = lane >> 2;
    int fc = (lane & 3) * 2;
    #pragma unroll
    for (int mt = 0; mt < 4; mt++) {
        int row0 = m0 + wm + mt * 16 + fr;
        #pragma unroll
        for (int nt = 0; nt < WN; nt++) {
            int n = n0 + wn + nt * 8 + fc;
            if (n < N) {
                float2 v0 = make_float2(acc[mt][nt][0], acc[mt][nt][1]);
                float2 v1 = make_float2(acc[mt][nt][2], acc[mt][nt][3]);
                if (bias) {
                    float2 bv = *(const float2*)(bias + n);
                    v0.x += bv.x; v0.y += bv.y;
                    v1.x += bv.x; v1.y += bv.y;
                }
                if (act == 1) {
                    v0.x = softplusf(v0.x); v0.y = softplusf(v0.y);
                    v1.x = softplusf(v1.x); v1.y = softplusf(v1.y);
                }
                if (resid) {
                    float2 r0 = *(const float2*)(resid + (size_t)row0 * ldc + n);
                    float2 r1 = *(const float2*)(resid + (size_t)(row0 + 8) * ldc + n);
                    v0.x += r0.x; v0.y += r0.y;
                    v1.x += r1.x; v1.y += r1.y;
                }
                *(float2*)(C + (size_t)row0 * ldc + n) = v0;
                *(float2*)(C + (size_t)(row0 + 8) * ldc + n) = v1;
            }
        }
    }
}

// ---------------- split-K reduction for x_proj ----------------
__global__ void xreduce_kernel() {
    int idx = blockIdx.x * blockDim.x + threadIdx.x;
    if (idx >= MROWS * XDIM) return;
    float s = 0.f;
    #pragma unroll
    for (int z = 0; z < XSPLIT; z++)
        s += g_xpart[(size_t)z * MROWS * XDIM + idx];
    g_xdbl[idx] = s;
}

// ---------------- selective scan: half-warp (16 lanes = 16 states) per (b,d)
__global__ void scan_kernel(const float* __restrict__ A_log,
                            const float* __restrict__ Dvec) {
    int half = threadIdx.x / 16;
    int ch = blockIdx.x * 16 + half;
    int lane = threadIdx.x & 15;
    int b = ch / DIN, d = ch % DIN;

    float An = -__expf(A_log[d * NS + lane]);
    float Dd = Dvec[d];

    const float* dptr = g_dlt  + (size_t)b * LL * DIN + d;
    const float* uptr = g_xbc  + (size_t)b * LL * DIN + d;
    const float* bptr = g_xdbl + (size_t)b * LL * XDIM + DTR + lane;
    const float* cptr = g_xdbl + (size_t)b * LL * XDIM + DTR + NS + lane;
    const float* zptr = g_xz   + (size_t)b * LL * (2 * DIN) + DIN + d;
    float* yptr = g_y + (size_t)b * LL * DIN + d;

    float h = 0.f;
    for (int t = 0; t < LL; t++) {
        float delta = dptr[(size_t)t * DIN];
        float u     = uptr[(size_t)t * DIN];
        float Bn    = bptr[(size_t)t * XDIM];
        float Cn    = cptr[(size_t)t * XDIM];
        float dA = __expf(delta * An);
        h = dA * h + delta * Bn * u;
        float p = h * Cn;
        p += __shfl_xor_sync(~0u, p, 8);
        p += __shfl_xor_sync(~0u, p, 4);
        p += __shfl_xor_sync(~0u, p, 2);
        p += __shfl_xor_sync(~0u, p, 1);
        if (lane == 0) {
            float z = zptr[(size_t)t * (2 * DIN)];
            float yv = p + u * Dd;
            yv *= z / (1.f + __expf(-z));
            yptr[(size_t)t * DIN] = yv;
        }
    }
}

// ---------------- launch ----------------
extern "C" void kernel_launch(void* const* d_in, const int* in_sizes, int n_in,
                              void* d_out, int out_size) {
    const int*   tokens    = (const int*)  d_in[0];
    const float* emb       = (const float*)d_in[1];
    const float* Wout_w    = (const float*)d_in[2];
    const float* Wout_b    = (const float*)d_in[3];
    const float* norm_w    = (const float*)d_in[4];
    const float* in_proj_w = (const float*)d_in[5];
    const float* conv_w    = (const float*)d_in[6];
    const float* conv_b    = (const float*)d_in[7];
    const float* x_proj_w  = (const float*)d_in[8];
    const float* dt_proj_w = (const float*)d_in[9];
    const float* dt_proj_b = (const float*)d_in[10];
    const float* A_log     = (const float*)d_in[11];
    const float* Dvec      = (const float*)d_in[12];
    const float* out_projw = (const float*)d_in[13];
    float* out = (float*)d_out;

    float *x, *xn, *xz, *xbc, *xdbl, *xpart, *dlt, *y;
    cudaGetSymbolAddress((void**)&x,     g_x);
    cudaGetSymbolAddress((void**)&xn,    g_xn);
    cudaGetSymbolAddress((void**)&xz,    g_xz);
    cudaGetSymbolAddress((void**)&xbc,   g_xbc);
    cudaGetSymbolAddress((void**)&xdbl,  g_xdbl);
    cudaGetSymbolAddress((void**)&xpart, g_xpart);
    cudaGetSymbolAddress((void**)&dlt,   g_dlt);
    cudaGetSymbolAddress((void**)&y,     g_y);

    // 3 warms so ncu (-s 5 -c 1) lands on the first big-tile GEMM (in_proj)
    warm_kernel<<<1, 32>>>();
    warm_kernel<<<1, 32>>>();
    warm_kernel<<<1, 32>>>();
    embed_kernel<<<(MROWS * DD + 255) / 256, 256>>>(tokens, emb);

    for (int l = 0; l < NLAYER; l++) {
        rmsnorm_kernel<<<MROWS, 256>>>(norm_w + (size_t)l * DD);

        // in_proj: (2048 x 3072), K=768 -- big tile 128x256, grid 16x12
        {
            dim3 g(MROWS / 128, 2 * DIN / 256);
            tgemm_kernel<8><<<g, 256>>>(xn,
                in_proj_w + (size_t)l * 2 * DIN * DD, nullptr, nullptr, xz,
                MROWS, 2 * DIN, DD, DD, 2 * DIN, 0, 0);
        }

        conv_silu_kernel<<<(MROWS * DIN + 255) / 256, 256>>>(
            conv_w + (size_t)l * DIN * DCV, conv_b + (size_t)l * DIN);

        // x_proj: (2048 x 80), K=1536, split-K=8 -> partials + reduce
        {
            dim3 g(MROWS / 128, 1, XSPLIT);
            tgemm_kernel<4><<<g, 256>>>(xbc,
                x_proj_w + (size_t)l * XDIM * DIN, nullptr, nullptr, xpart,
                MROWS, XDIM, DIN, DIN, XDIM, 0, DIN / XSPLIT);
            xreduce_kernel<<<(MROWS * XDIM + 255) / 256, 256>>>();
        }

        // dt_proj + bias + softplus: (2048 x 1536), K=48
        {
            dim3 g(MROWS / 128, DIN / 128);
            tgemm_kernel<4><<<g, 256>>>(xdbl,
                dt_proj_w + (size_t)l * DIN * DTR,
                dt_proj_b + (size_t)l * DIN, nullptr, dlt,
                MROWS, DIN, DTR, XDIM, DIN, 1, 0);
        }

        scan_kernel<<<(BB * DIN) / 16, 256>>>(A_log + (size_t)l * DIN * NS,
                                              Dvec + (size_t)l * DIN);

        // out_proj + residual: (2048 x 768), K=1536
        {
            dim3 g(MROWS / 128, DD / 128);
            tgemm_kernel<4><<<g, 256>>>(y,
                out_projw + (size_t)l * DD * DIN, nullptr, x, x,
                MROWS, DD, DIN, DIN, DD, 0, 0);
        }
    }

    // logits: (2048 x 32000), K=768, + bias -- big tile, grid 16x125
    {
        dim3 g(MROWS / 128, VV / 256);
        tgemm_kernel<8><<<g, 256>>>(x, Wout_w, Wout_b, nullptr, out,
                                    MROWS, VV, DD, DD, VV, 0, 0);
    }
}

// round 7
// speedup vs baseline: 1.9275x; 1.8673x over previous
#include <cuda_runtime.h>
#include <math.h>
#include <stdint.h>

// ---------------- problem constants ----------------
#define BB   2
#define LL   1024
#define DD   768
#define VV   32000
#define NLAYER 4
#define DIN  1536          // d_inner
#define NS   16            // d_state
#define DCV  4             // d_conv
#define DTR  48            // dt_rank
#define XDIM (DTR + 2*NS)  // 80
#define MROWS (BB*LL)      // 2048
#define XSPLIT 8           // split-K factor for x_proj
#define OSPLIT 2           // split-K factor for out_proj

// ---------------- device scratch (no allocation allowed) ----------------
__device__ float g_x    [MROWS*DD];
__device__ float g_xn   [MROWS*DD];
__device__ float g_xz   [MROWS*2*DIN];
__device__ float g_xbc  [MROWS*DIN];     // u (contiguous, for x_proj GEMM)
__device__ float g_du   [MROWS*DIN*2];   // packed (delta, u) for scan
__device__ float g_xdbl [MROWS*XDIM];
__device__ float g_xpart[XSPLIT*MROWS*XDIM];
__device__ float g_ypart[OSPLIT*MROWS*DD];
__device__ float g_y    [MROWS*DIN];

// ---------------- helpers ----------------
__device__ __forceinline__ float softplusf(float x) {
    return fmaxf(x, 0.f) + log1pf(expf(-fabsf(x)));
}
__device__ __forceinline__ float siluf(float x) {
    return x / (1.f + expf(-x));
}
__device__ __forceinline__ uint32_t to_tf32(float f) {
    uint32_t u;
    asm("cvt.rna.tf32.f32 %0, %1;" : "=r"(u) : "f"(f));
    return u;
}

// ---------------- warmup/dummy: shifts ncu capture window ----------------
__global__ void warm_kernel() {
    if (threadIdx.x == 0) g_xpart[0] = 0.f;
}

// ---------------- embedding gather ----------------
__global__ void embed_kernel(const int* __restrict__ tok,
                             const float* __restrict__ emb) {
    int idx = blockIdx.x * blockDim.x + threadIdx.x;
    if (idx >= MROWS * DD) return;
    int row = idx / DD, d = idx - row * DD;
    g_x[idx] = emb[tok[row] * DD + d];
}

// ---------------- rmsnorm: one block per row ----------------
__global__ void rmsnorm_kernel(const float* __restrict__ w) {
    int row = blockIdx.x;
    const float* xr = g_x + row * DD;
    float s = 0.f;
    for (int i = threadIdx.x; i < DD; i += 256) { float v = xr[i]; s += v * v; }
    __shared__ float red[8];
    #pragma unroll
    for (int o = 16; o; o >>= 1) s += __shfl_xor_sync(~0u, s, o);
    if ((threadIdx.x & 31) == 0) red[threadIdx.x >> 5] = s;
    __syncthreads();
    if (threadIdx.x < 8) {
        float v = red[threadIdx.x];
        #pragma unroll
        for (int o = 4; o; o >>= 1) v += __shfl_xor_sync(0xff, v, o);
        if (threadIdx.x == 0) red[0] = v;
    }
    __syncthreads();
    float rstd = rsqrtf(red[0] / (float)DD + 1e-5f);
    for (int i = threadIdx.x; i < DD; i += 256)
        g_xn[row * DD + i] = xr[i] * rstd * w[i];
}

// ---------------- causal depthwise conv (DC=4) + silu ----------------
// writes u to g_xbc (contiguous, x_proj input) and g_du[.].y (scan input)
__global__ void conv_silu_kernel(const float* __restrict__ w,
                                 const float* __restrict__ bias) {
    int idx = blockIdx.x * blockDim.x + threadIdx.x;
    if (idx >= MROWS * DIN) return;
    int c = idx % DIN;
    int row = idx / DIN;
    int t = row % LL;
    float acc = bias[c];
    #pragma unroll
    for (int j = 0; j < DCV; j++) {
        int tt = t - (DCV - 1) + j;
        if (tt >= 0)
            acc += w[c * DCV + j] * g_xz[(row - (DCV - 1) + j) * (2 * DIN) + c];
    }
    float s = siluf(acc);
    g_xbc[idx] = s;
    g_du[idx * 2 + 1] = s;
}

// ---------------- TF32 tensor-core GEMM (R2 body + split-K + cstride) -----
// C[M,N] = A[M,K] @ W[N,K]^T (+bias)(+softplus)(+resid)
// Tile 128x128, BK=16, 8 warps (each warp 64x32 via 4x4 m16n8k8 mma).
// kchunk>0: split-K; CTA z covers k in [z*kchunk,..), partials at C+z*M*ldc.
// cstride: element stride of C (2 => interleaved write into g_du.x).
__global__ void __launch_bounds__(256)
tgemm_kernel(const float* __restrict__ A, const float* __restrict__ W,
             const float* __restrict__ bias, const float* __restrict__ resid,
             float* __restrict__ C,
             int M, int N, int K, int lda, int ldc, int act,
             int kchunk, int cstride) {
    __shared__ uint32_t As[128][20];
    __shared__ uint32_t Bs[128][20];

    int tid = threadIdx.x;
    int m0 = blockIdx.y * 128, n0 = blockIdx.x * 128;
    int lane = tid & 31, warp = tid >> 5;
    int wm = (warp & 1) * 64;
    int wn = (warp >> 1) * 32;

    int kbase = 0, kcount = K;
    if (kchunk > 0) {
        kbase = blockIdx.z * kchunk;
        kcount = kchunk;
        C += (size_t)blockIdx.z * M * ldc;
    }

    int sr = tid >> 2;
    int sc = (tid & 3) * 4;

    const float* Aptr0 = A + (size_t)(m0 + sr) * lda + kbase + sc;
    const float* Aptr1 = A + (size_t)(m0 + sr + 64) * lda + kbase + sc;
    bool wv0 = (n0 + sr) < N;
    bool wv1 = (n0 + sr + 64) < N;
    const float* Wptr0 = W + (size_t)(n0 + sr) * K + kbase + sc;
    const float* Wptr1 = W + (size_t)(n0 + sr + 64) * K + kbase + sc;

    float acc[4][4][4];
    #pragma unroll
    for (int i = 0; i < 4; i++)
        #pragma unroll
        for (int j = 0; j < 4; j++)
            #pragma unroll
            for (int r = 0; r < 4; r++) acc[i][j][r] = 0.f;

    for (int ks = 0; ks < kcount; ks += 16) {
        float4 a0 = *(const float4*)(Aptr0 + ks);
        float4 a1 = *(const float4*)(Aptr1 + ks);
        float4 w0 = wv0 ? *(const float4*)(Wptr0 + ks) : make_float4(0,0,0,0);
        float4 w1 = wv1 ? *(const float4*)(Wptr1 + ks) : make_float4(0,0,0,0);
        As[sr][sc + 0] = to_tf32(a0.x); As[sr][sc + 1] = to_tf32(a0.y);
        As[sr][sc + 2] = to_tf32(a0.z); As[sr][sc + 3] = to_tf32(a0.w);
        As[sr + 64][sc + 0] = to_tf32(a1.x); As[sr + 64][sc + 1] = to_tf32(a1.y);
        As[sr + 64][sc + 2] = to_tf32(a1.z); As[sr + 64][sc + 3] = to_tf32(a1.w);
        Bs[sr][sc + 0] = to_tf32(w0.x); Bs[sr][sc + 1] = to_tf32(w0.y);
        Bs[sr][sc + 2] = to_tf32(w0.z); Bs[sr][sc + 3] = to_tf32(w0.w);
        Bs[sr + 64][sc + 0] = to_tf32(w1.x); Bs[sr + 64][sc + 1] = to_tf32(w1.y);
        Bs[sr + 64][sc + 2] = to_tf32(w1.z); Bs[sr + 64][sc + 3] = to_tf32(w1.w);
        __syncthreads();

        #pragma unroll
        for (int kk = 0; kk < 16; kk += 8) {
            uint32_t af[4][4], bf[4][2];
            int k0 = kk + (lane & 3);
            int fr = lane >> 2;
            #pragma unroll
            for (int mt = 0; mt < 4; mt++) {
                int row = wm + mt * 16 + fr;
                af[mt][0] = As[row][k0];
                af[mt][1] = As[row + 8][k0];
                af[mt][2] = As[row][k0 + 4];
                af[mt][3] = As[row + 8][k0 + 4];
            }
            #pragma unroll
            for (int nt = 0; nt < 4; nt++) {
                int col = wn + nt * 8 + fr;
                bf[nt][0] = Bs[col][k0];
                bf[nt][1] = Bs[col][k0 + 4];
            }
            #pragma unroll
            for (int mt = 0; mt < 4; mt++)
                #pragma unroll
                for (int nt = 0; nt < 4; nt++) {
                    asm volatile(
                        "mma.sync.aligned.m16n8k8.row.col.f32.tf32.tf32.f32 "
                        "{%0,%1,%2,%3}, {%4,%5,%6,%7}, {%8,%9}, {%0,%1,%2,%3};"
                        : "+f"(acc[mt][nt][0]), "+f"(acc[mt][nt][1]),
                          "+f"(acc[mt][nt][2]), "+f"(acc[mt][nt][3])
                        : "r"(af[mt][0]), "r"(af[mt][1]),
                          "r"(af[mt][2]), "r"(af[mt][3]),
                          "r"(bf[nt][0]), "r"(bf[nt][1]));
                }
        }
        __syncthreads();
    }

    int fr = lane >> 2;
    int fc = (lane & 3) * 2;
    #pragma unroll
    for (int mt = 0; mt < 4; mt++) {
        int row0 = m0 + wm + mt * 16 + fr;
        #pragma unroll
        for (int nt = 0; nt < 4; nt++) {
            int col0 = n0 + wn + nt * 8 + fc;
            #pragma unroll
            for (int r = 0; r < 4; r++) {
                int m = row0 + (r >> 1) * 8;
                int n = col0 + (r & 1);
                if (n < N) {
                    float v = acc[mt][nt][r];
                    if (bias)  v += bias[n];
                    if (act == 1) v = softplusf(v);
                    if (resid) v += resid[(size_t)m * ldc + n];
                    C[((size_t)m * ldc + n) * cstride] = v;
                }
            }
        }
    }
}

// ---------------- split-K reductions ----------------
__global__ void xreduce_kernel() {
    int idx = blockIdx.x * blockDim.x + threadIdx.x;
    if (idx >= MROWS * XDIM) return;
    float s = 0.f;
    #pragma unroll
    for (int z = 0; z < XSPLIT; z++)
        s += g_xpart[(size_t)z * MROWS * XDIM + idx];
    g_xdbl[idx] = s;
}
__global__ void yreduce_kernel() {
    int idx = blockIdx.x * blockDim.x + threadIdx.x;
    if (idx >= MROWS * DD) return;
    g_x[idx] += g_ypart[idx] + g_ypart[MROWS * DD + idx];
}

// ---------------- selective scan, 8-timestep batches ----------------
// half-warp (16 lanes = 16 states) per (b,d); loads batched (MLP), 8
// independent shfl trees interleaved so their latencies overlap.
#define STB 8
__global__ void scan_kernel(const float* __restrict__ A_log,
                            const float* __restrict__ Dvec) {
    int half = threadIdx.x / 16;
    int ch = blockIdx.x * 16 + half;
    int lane = threadIdx.x & 15;
    int b = ch / DIN, d = ch % DIN;

    float An = -__expf(A_log[d * NS + lane]);
    float Dd = Dvec[d];

    const float2* duptr = (const float2*)g_du + (size_t)b * LL * DIN + d;
    const float* bcbase = g_xdbl + (size_t)b * LL * XDIM + DTR;
    const float* zptr = g_xz + (size_t)b * LL * (2 * DIN) + DIN + d;
    float* yptr = g_y + (size_t)b * LL * DIN + d;

    float h = 0.f;
    for (int t0 = 0; t0 < LL; t0 += STB) {
        float2 du[STB]; float Bn[STB], Cn[STB];
        #pragma unroll
        for (int i = 0; i < STB; i++) {
            du[i] = duptr[(size_t)(t0 + i) * DIN];
            Bn[i] = bcbase[(size_t)(t0 + i) * XDIM + lane];
            Cn[i] = bcbase[(size_t)(t0 + i) * XDIM + NS + lane];
        }
        float zv[STB];
        #pragma unroll
        for (int i = 0; i < STB; i++)
            zv[i] = zptr[(size_t)(t0 + i) * (2 * DIN)];

        float p[STB];
        #pragma unroll
        for (int i = 0; i < STB; i++) {
            float dA = __expf(du[i].x * An);
            h = fmaf(dA, h, du[i].x * Bn[i] * du[i].y);
            p[i] = h * Cn[i];
        }
        // 8 interleaved butterfly trees (independent chains)
        #pragma unroll
        for (int o = 8; o; o >>= 1) {
            #pragma unroll
            for (int i = 0; i < STB; i++)
                p[i] += __shfl_xor_sync(~0u, p[i], o);
        }
        if (lane == 0) {
            #pragma unroll
            for (int i = 0; i < STB; i++) {
                float yv = p[i] + du[i].y * Dd;
                yv *= zv[i] / (1.f + __expf(-zv[i]));
                yptr[(size_t)(t0 + i) * DIN] = yv;
            }
        }
    }
}

// ---------------- launch ----------------
extern "C" void kernel_launch(void* const* d_in, const int* in_sizes, int n_in,
                              void* d_out, int out_size) {
    const int*   tokens    = (const int*)  d_in[0];
    const float* emb       = (const float*)d_in[1];
    const float* Wout_w    = (const float*)d_in[2];
    const float* Wout_b    = (const float*)d_in[3];
    const float* norm_w    = (const float*)d_in[4];
    const float* in_proj_w = (const float*)d_in[5];
    const float* conv_w    = (const float*)d_in[6];
    const float* conv_b    = (const float*)d_in[7];
    const float* x_proj_w  = (const float*)d_in[8];
    const float* dt_proj_w = (const float*)d_in[9];
    const float* dt_proj_b = (const float*)d_in[10];
    const float* A_log     = (const float*)d_in[11];
    const float* Dvec      = (const float*)d_in[12];
    const float* out_projw = (const float*)d_in[13];
    float* out = (float*)d_out;

    float *x, *xn, *xz, *xbc, *du, *xdbl, *xpart, *ypart, *y;
    cudaGetSymbolAddress((void**)&x,     g_x);
    cudaGetSymbolAddress((void**)&xn,    g_xn);
    cudaGetSymbolAddress((void**)&xz,    g_xz);
    cudaGetSymbolAddress((void**)&xbc,   g_xbc);
    cudaGetSymbolAddress((void**)&du,    g_du);
    cudaGetSymbolAddress((void**)&xdbl,  g_xdbl);
    cudaGetSymbolAddress((void**)&xpart, g_xpart);
    cudaGetSymbolAddress((void**)&ypart, g_ypart);
    cudaGetSymbolAddress((void**)&y,     g_y);

    // 1 warm => ncu index-3 capture lands on in_proj
    warm_kernel<<<1, 32>>>();
    embed_kernel<<<(MROWS * DD + 255) / 256, 256>>>(tokens, emb);

    for (int l = 0; l < NLAYER; l++) {
        rmsnorm_kernel<<<MROWS, 256>>>(norm_w + (size_t)l * DD);

        // in_proj: (2048 x 3072), K=768
        {
            dim3 g(2 * DIN / 128, MROWS / 128);
            tgemm_kernel<<<g, 256>>>(xn, in_proj_w + (size_t)l * 2 * DIN * DD,
                                     nullptr, nullptr, xz,
                                     MROWS, 2 * DIN, DD, DD, 2 * DIN, 0, 0, 1);
        }

        conv_silu_kernel<<<(MROWS * DIN + 255) / 256, 256>>>(
            conv_w + (size_t)l * DIN * DCV, conv_b + (size_t)l * DIN);

        // x_proj: (2048 x 80), K=1536, split-K=8 (16 -> 128 CTAs)
        {
            dim3 g(1, MROWS / 128, XSPLIT);
            tgemm_kernel<<<g, 256>>>(xbc, x_proj_w + (size_t)l * XDIM * DIN,
                                     nullptr, nullptr, xpart,
                                     MROWS, XDIM, DIN, DIN, XDIM, 0,
                                     DIN / XSPLIT, 1);
            xreduce_kernel<<<(MROWS * XDIM + 255) / 256, 256>>>();
        }

        // dt_proj + bias + softplus -> g_du[.].x (cstride=2): K=48
        {
            dim3 g(DIN / 128, MROWS / 128);
            tgemm_kernel<<<g, 256>>>(xdbl, dt_proj_w + (size_t)l * DIN * DTR,
                                     dt_proj_b + (size_t)l * DIN, nullptr, du,
                                     MROWS, DIN, DTR, XDIM, DIN, 1, 0, 2);
        }

        scan_kernel<<<(BB * DIN) / 16, 256>>>(A_log + (size_t)l * DIN * NS,
                                              Dvec + (size_t)l * DIN);

        // out_proj: (2048 x 768), K=1536, split-K=2 (96 -> 192 CTAs)
        {
            dim3 g(DD / 128, MROWS / 128, OSPLIT);
            tgemm_kernel<<<g, 256>>>(y, out_projw + (size_t)l * DD * DIN,
                                     nullptr, nullptr, ypart,
                                     MROWS, DD, DIN, DIN, DD, 0,
                                     DIN / OSPLIT, 1);
            yreduce_kernel<<<(MROWS * DD + 255) / 256, 256>>>();
        }
    }

    // logits: (2048 x 32000), K=768, + bias
    {
        dim3 g(VV / 128, MROWS / 128);
        tgemm_kernel<<<g, 256>>>(x, Wout_w, Wout_b, nullptr, out,
                                 MROWS, VV, DD, DD, VV, 0, 0, 1);
    }
}